// round 3
// baseline (speedup 1.0000x reference)
#include <cuda_runtime.h>
#include <cstdint>

#define BS 8
#define CH 256
#define HW 16384
#define NK 19
#define NQ 2975
#define INVT 5.0f
#define LOG2E 1.4426950408889634f
#define LN2   0.6931471805599453f

#define NBLK1 296
#define NTILES (BS * HW / 32)
#define TILES_PER_B (HW / 32)
#define QSCALE 524288.0f
#define INV_QSCALE (1.0f / 524288.0f)
#define CST 262

// ---------------- device scratch (no runtime alloc allowed) ----------------
__device__ float g_partial[NBLK1 * NK * CH];
__device__ int   g_cnt[NBLK1 * NK];
__device__ float g_sums[NK * CH];
__device__ float g_sqpart[NK * 8];
__device__ float g_scale[NK];
__device__ float g_present[NK];
__device__ float g_contrib[CH * NK];

__device__ __forceinline__ float ex2f(float x) {
    float y; asm("ex2.approx.ftz.f32 %0, %1;" : "=f"(y) : "f"(x)); return y;
}

// ============================================================
// Kernel 1: argmax(res) + res->out copy + per-class channel sums.
// 256 threads / block; tile = 32 pixels. Warp w owns channels [32w,32w+32).
// ============================================================
__global__ __launch_bounds__(256, 2)
void k1_sums(const float* __restrict__ fea, const float* __restrict__ res,
             float* __restrict__ out) {
    __shared__ __align__(16) int ssum[NK * CST];
    __shared__ float sv[8][32];
    __shared__ int   sbk[8][32];
    __shared__ unsigned char spred[32];
    __shared__ int scnt[NK];

    const int tid  = threadIdx.x;
    const int lane = tid & 31;
    const int w    = tid >> 5;

    for (int i = tid; i < NK * CST; i += 256) ssum[i] = 0;
    if (tid < NK) scnt[tid] = 0;
    __syncthreads();

    for (int t = blockIdx.x; t < NTILES; t += NBLK1) {
        const int b  = t / TILES_PER_B;
        const int p0 = (t % TILES_PER_B) << 5;

        // ---- argmax over 19 logit rows (warp w owns k = w, w+8, w+16) ----
        float bv = -3.4e38f; int bk = NK;
        #pragma unroll
        for (int kk = 0; kk < 3; kk++) {
            int k = w + kk * 8;
            if (k < NK) {
                int idx = (b * NK + k) * HW + p0 + lane;
                float v = res[idx];
                out[idx] = v;                        // fused res copy
                if (v > bv) { bv = v; bk = k; }      // ascending k -> first max wins
            }
        }
        sv[w][lane] = bv; sbk[w][lane] = bk;
        __syncthreads();
        if (w == 0) {
            float Bv = sv[0][lane]; int Bk = sbk[0][lane];
            #pragma unroll
            for (int j = 1; j < 8; j++) {
                float v = sv[j][lane]; int kk2 = sbk[j][lane];
                if (v > Bv || (v == Bv && kk2 < Bk)) { Bv = v; Bk = kk2; }
            }
            spred[lane] = (unsigned char)Bk;
            unsigned m = __match_any_sync(0xffffffffu, Bk);
            if ((m & ((1u << lane) - 1u)) == 0) scnt[Bk] += __popc(m);
        }
        __syncthreads();

        // ---- channel sweep: group-reduce per predicted class ----
        const int pc = (int)spred[lane];
        const unsigned mask = __match_any_sync(0xffffffffu, pc);
        const bool head = ((mask & ((1u << lane) - 1u)) == 0);
        const int hbase = pc * CST + w * 32;
        const float* fbase = fea + ((long)(b * CH + w * 32)) * HW + p0 + lane;

        #pragma unroll
        for (int c0 = 0; c0 < 32; c0 += 8) {
            float v[8];
            #pragma unroll
            for (int j = 0; j < 8; j++) v[j] = fbase[((long)(c0 + j)) << 14];
            int gi[8];
            #pragma unroll
            for (int j = 0; j < 8; j++) gi[j] = __float2int_rn(v[j] * QSCALE);
            #pragma unroll
            for (int j = 0; j < 8; j++) gi[j] = __reduce_add_sync(mask, gi[j]);
            if (head) {
                #pragma unroll
                for (int j = 0; j < 8; j += 2) {
                    int2* p = (int2*)&ssum[hbase + c0 + j];
                    int2 cur = *p; cur.x += gi[j]; cur.y += gi[j + 1]; *p = cur;
                }
            }
        }
        __syncthreads();
    }

    for (int i = tid; i < NK * CH; i += 256) {
        int k = i >> 8, c = i & 255;
        g_partial[blockIdx.x * (NK * CH) + i] = (float)ssum[k * CST + c] * INV_QSCALE;
    }
    if (tid < NK) g_cnt[blockIdx.x * NK + tid] = scnt[tid];
}

// ============================================================
// Kernel 2a: reduce partials -> g_sums, per-(k,chunk) sum of squares.
// grid = 19*8 blocks, 256 threads.
// ============================================================
__global__ void k2a_reduce() {
    const int k = blockIdx.x >> 3;
    const int chunk = blockIdx.x & 7;
    const int lane = threadIdx.x & 31;
    const int g = threadIdx.x >> 5;
    const int c = chunk * 32 + lane;

    float s = 0.0f;
    for (int blk = g; blk < NBLK1; blk += 8)
        s += g_partial[blk * (NK * CH) + k * CH + c];
    __shared__ float sm[8][33];
    sm[g][lane] = s;
    __syncthreads();
    if (g == 0) {
        float tot = 0.0f;
        #pragma unroll
        for (int j = 0; j < 8; j++) tot += sm[j][lane];
        g_sums[k * CH + c] = tot;
        float sq = tot * tot;
        #pragma unroll
        for (int off = 16; off > 0; off >>= 1) sq += __shfl_xor_sync(0xffffffffu, sq, off);
        if (lane == 0) g_sqpart[k * 8 + chunk] = sq;
    }
}

// ============================================================
// Kernel 2b: counts + per-class key scale.
// keys = normalize(sums/max(cnt,1)) = sums / max(||sums||, max(cnt,1)*1e-12)
// ============================================================
__global__ void k2b_scale() {
    __shared__ int scnt2[NK][8];
    const int t = threadIdx.x;
    if (t < NK * 8) {
        int k = t >> 3, part = t & 7;
        int cs = 0;
        for (int blk = part; blk < NBLK1; blk += 8) cs += g_cnt[blk * NK + k];
        scnt2[k][part] = cs;
    }
    __syncthreads();
    if (t < NK) {
        int cnt = 0;
        #pragma unroll
        for (int j = 0; j < 8; j++) cnt += scnt2[t][j];
        float sq = 0.0f;
        #pragma unroll
        for (int j = 0; j < 8; j++) sq += g_sqpart[t * 8 + j];
        float nrm = sqrtf(sq);
        float cp = fmaxf((float)cnt, 1.0f);
        g_scale[t] = 1.0f / fmaxf(nrm, cp * 1e-12f);
        g_present[t] = (cnt > 0) ? 1.0f : 0.0f;
    }
}

// ============================================================
// Kernel 3: per-channel logsumexp over 2Q logits. grid = 256 (one per c).
// queues read exactly once; qsum on the fly; 19 reg accumulators.
// ============================================================
__global__ __launch_bounds__(256, 2)
void k3_lse(const float* __restrict__ queues) {
    const int c = blockIdx.x;
    const int t = threadIdx.x;
    const int lane = t & 31;
    const int w = t >> 5;

    __shared__ float sb[NK];          // keys[k][c] * invT * log2e
    __shared__ float sred[NK][9];
    if (t < NK) sb[t] = g_sums[t * CH + c] * g_scale[t] * (INVT * LOG2E);
    __syncthreads();

    float bs[NK];
    #pragma unroll
    for (int k = 0; k < NK; k++) bs[k] = sb[k];
    float acc[NK];
    #pragma unroll
    for (int k = 0; k < NK; k++) acc[k] = 0.0f;

    for (int q = t; q < NQ; q += 256) {
        float qv[NK];
        #pragma unroll
        for (int k = 0; k < NK; k++)
            qv[k] = queues[((long)(k * CH + c)) * NQ + q];
        float qs = 0.0f;
        #pragma unroll
        for (int k = 0; k < NK; k++) qs += qv[k];
        #pragma unroll
        for (int k = 0; k < NK; k++) {
            float u  = bs[k] * qv[k];        // l_pos / T * log2e
            float wv = bs[k] * qs - u;       // l_neg / T * log2e
            acc[k] += ex2f(u) + ex2f(wv);
        }
    }
    #pragma unroll
    for (int k = 0; k < NK; k++) {
        #pragma unroll
        for (int off = 16; off > 0; off >>= 1)
            acc[k] += __shfl_xor_sync(0xffffffffu, acc[k], off);
    }
    if (lane == 0) {
        #pragma unroll
        for (int k = 0; k < NK; k++) sred[k][w] = acc[k];
    }
    __syncthreads();
    if (t < NK) {
        float tot = 0.0f;
        #pragma unroll
        for (int j = 0; j < 8; j++) tot += sred[t][j];
        float q0 = queues[((long)(t * CH + c)) * NQ];
        // lse - logit0 (natural log)
        g_contrib[c * NK + t] = (log2f(tot) - sb[t] * q0) * LN2;
    }
}

// ============================================================
// Kernel 4: loss = sum_k present[k] * mean_c contrib[c][k]
// ============================================================
__global__ void k4_loss(float* __restrict__ out_loss) {
    __shared__ float red[NK];
    const int t = threadIdx.x;
    const int lane = t & 31;
    if (t < NK) red[t] = 0.0f;
    __syncthreads();
    #pragma unroll
    for (int k = 0; k < NK; k++) {
        float s = g_contrib[t * NK + k];
        #pragma unroll
        for (int off = 16; off > 0; off >>= 1)
            s += __shfl_xor_sync(0xffffffffu, s, off);
        if (lane == 0) atomicAdd(&red[k], s);
    }
    __syncthreads();
    if (t == 0) {
        float loss = 0.0f;
        #pragma unroll
        for (int k = 0; k < NK; k++) loss += g_present[k] * red[k] * (1.0f / CH);
        *out_loss = loss;
    }
}

extern "C" void kernel_launch(void* const* d_in, const int* in_sizes, int n_in,
                              void* d_out, int out_size) {
    const float* fea    = (const float*)d_in[0];
    const float* res    = (const float*)d_in[1];
    const float* queues = (const float*)d_in[2];
    float* out = (float*)d_out;
    float* out_loss = out + (out_size - 1);

    k1_sums<<<NBLK1, 256>>>(fea, res, out);
    k2a_reduce<<<NK * 8, 256>>>();
    k2b_scale<<<1, 256>>>();
    k3_lse<<<CH, 256>>>(queues);
    k4_loss<<<1, 256>>>(out_loss);
}

// round 5
// speedup vs baseline: 3.5760x; 3.5760x over previous
#include <cuda_runtime.h>
#include <cstdint>

#define BS 8
#define CH 256
#define HW 16384
#define NK 19
#define NQ 2975
#define LOG2E 1.4426950408889634f
#define LN2   0.6931471805599453f
#define SB_FACT (5.0f * LOG2E)      /* (1/T) * log2(e) */

#define NBLK1 296
#define SP 64
#define NSTRIPS (BS * HW / SP)      /* 2048 */
#define CST2 257                    /* ssum row stride (odd) */

#define QPARTS 4
#define QCHUNK 744

/* dynamic smem layout for k1 (in 4-byte words) */
#define TILE_OFF  0                 /* 256*64 = 16384 words */
#define SSUM_OFF  16384             /* 19*257 = 4883 words  */
#define SV_OFF    21267             /* 4*64                 */
#define SBK_OFF   21523             /* 4*64                 */
#define SPRED_OFF 21779             /* 16 words (64 bytes)  */
#define K1_WORDS  21795
#define K1_SMEM_BYTES (K1_WORDS * 4)

/* ---------------- device scratch ---------------- */
__device__ float g_partial[NBLK1 * NK * CH];
__device__ int   g_cnt[NBLK1 * NK];
__device__ float g_sums[NK * CH];
__device__ float g_sqpart[NK * 8];
__device__ float g_scale[NK];
__device__ float g_present[NK];
__device__ float g_lsepart[QPARTS * NK * CH];
__device__ float g_sbq0[NK * CH];

__device__ __forceinline__ float ex2f(float x) {
    float y; asm("ex2.approx.ftz.f32 %0, %1;" : "=f"(y) : "f"(x)); return y;
}

// ============================================================
// Kernel 1: fused argmax + res->out copy + per-class channel sums.
// Block = 256 threads, strip = 64 pixels of one image.
// ============================================================
__global__ void k1_fused(const float* __restrict__ fea,
                         const float* __restrict__ res,
                         float* __restrict__ out) {
    extern __shared__ float sm[];
    float* tile = sm + TILE_OFF;
    float* ssum = sm + SSUM_OFF;
    float* sv2  = sm + SV_OFF;
    int*   sbk2 = (int*)(sm + SBK_OFF);
    unsigned char* spred  = (unsigned char*)(sm + SPRED_OFF);
    unsigned*      spredw = (unsigned*)(sm + SPRED_OFF);

    const int tid  = threadIdx.x;
    const int lane = tid & 31;
    const int w    = tid >> 5;

    for (int i = tid; i < NK * CST2; i += 256) ssum[i] = 0.0f;
    int creg = 0;                       // warp-0 lanes < NK: class counts
    __syncthreads();

    const int px_r = tid & 63;          // res-phase pixel within strip
    const int ks   = tid >> 6;          // k-slice 0..3

    for (int s = blockIdx.x; s < NSTRIPS; s += NBLK1) {
        const int b  = s >> 8;
        const int p0 = (s & 255) << 6;

        // ---- res phase: copy + per-slice argmax (k = ks, ks+4, ...) ----
        float bv = -3.4e38f; int bk = NK;
        #pragma unroll
        for (int j = 0; j < 5; j++) {
            int k = ks + (j << 2);
            if (k < NK) {
                int idx = ((b * NK + k) << 14) + p0 + px_r;
                float v = res[idx];
                out[idx] = v;
                if (v > bv) { bv = v; bk = k; }   // ascending k: first max wins
            }
        }
        sv2[(ks << 6) + px_r] = bv;
        sbk2[(ks << 6) + px_r] = bk;

        // ---- stage A: fea tile (256 ch x 64 px) -> smem, XOR-swizzled ----
        const float* fb = fea + (((long)(b * CH)) << 14) + p0;
        #pragma unroll 4
        for (int it = 0; it < 32; it++) {
            int row = w + (it << 3);
            const float* fr = fb + (((long)row) << 14);
            float a0 = fr[lane];
            float a1 = fr[lane + 32];
            int rm = row & 31;
            int base = row << 6;
            tile[base + (lane ^ rm)] = a0;
            tile[base + ((lane + 32) ^ rm)] = a1;
        }
        __syncthreads();

        // ---- combine slice argmaxes -> spred bytes ----
        if (tid < 64) {
            float Bv = sv2[tid]; int Bk = sbk2[tid];
            #pragma unroll
            for (int j = 1; j < 4; j++) {
                float v = sv2[(j << 6) + tid]; int kk = sbk2[(j << 6) + tid];
                if (v > Bv || (v == Bv && kk < Bk)) { Bv = v; Bk = kk; }
            }
            spred[tid] = (unsigned char)Bk;
        }
        __syncthreads();

        // ---- stage C: thread = channel, walk 64 pixels ----
        const int cxor  = tid & 31;
        const int cbase = tid << 6;
        #pragma unroll 4
        for (int p4 = 0; p4 < 16; p4++) {
            unsigned pw = spredw[p4];
            #pragma unroll
            for (int j = 0; j < 4; j++) {
                int p  = (p4 << 2) + j;
                int pc = (pw >> (j * 8)) & 0xFF;
                float v = tile[cbase + (p ^ cxor)];
                ssum[pc * CST2 + tid] += v;
                if (w == 0) creg += (pc == lane) ? 1 : 0;
            }
        }
        __syncthreads();
    }

    // ---- flush partials ----
    for (int i = tid; i < NK * CH; i += 256) {
        int k = i >> 8, c = i & 255;
        g_partial[blockIdx.x * (NK * CH) + i] = ssum[k * CST2 + c];
    }
    if (w == 0 && lane < NK) g_cnt[blockIdx.x * NK + lane] = creg;
}

// ============================================================
// Kernel 2a: reduce partials -> g_sums + per-(k,chunk) sum of squares.
// ============================================================
__global__ void k2a_reduce() {
    const int k = blockIdx.x >> 3;
    const int chunk = blockIdx.x & 7;
    const int lane = threadIdx.x & 31;
    const int g = threadIdx.x >> 5;
    const int c = chunk * 32 + lane;

    float s = 0.0f;
    for (int blk = g; blk < NBLK1; blk += 8)
        s += g_partial[blk * (NK * CH) + k * CH + c];
    __shared__ float smr[8][33];
    smr[g][lane] = s;
    __syncthreads();
    if (g == 0) {
        float tot = 0.0f;
        #pragma unroll
        for (int j = 0; j < 8; j++) tot += smr[j][lane];
        g_sums[k * CH + c] = tot;
        float sq = tot * tot;
        #pragma unroll
        for (int off = 16; off > 0; off >>= 1) sq += __shfl_xor_sync(0xffffffffu, sq, off);
        if (lane == 0) g_sqpart[k * 8 + chunk] = sq;
    }
}

// ============================================================
// Kernel 2b: counts + per-class key scale + present flags.
// keys = normalize(sums/max(cnt,1)) = sums / max(||sums||, max(cnt,1)*1e-12)
// ============================================================
__global__ void k2b_scale() {
    __shared__ int scnt2[NK][8];
    const int t = threadIdx.x;
    if (t < NK * 8) {
        int k = t >> 3, part = t & 7;
        int cs = 0;
        for (int blk = part; blk < NBLK1; blk += 8) cs += g_cnt[blk * NK + k];
        scnt2[k][part] = cs;
    }
    __syncthreads();
    if (t < NK) {
        int cnt = 0;
        #pragma unroll
        for (int j = 0; j < 8; j++) cnt += scnt2[t][j];
        float sq = 0.0f;
        #pragma unroll
        for (int j = 0; j < 8; j++) sq += g_sqpart[t * 8 + j];
        float nrm = sqrtf(sq);
        float cp = fmaxf((float)cnt, 1.0f);
        g_scale[t] = 1.0f / fmaxf(nrm, cp * 1e-12f);
        g_present[t] = (cnt > 0) ? 1.0f : 0.0f;
    }
}

// ============================================================
// Kernel 3: partial exp-sums over a quarter of the 2Q logits.
// grid = 256 channels x 4 q-parts.
// ============================================================
__global__ __launch_bounds__(256) void k3_lse(const float* __restrict__ queues) {
    const int c    = blockIdx.x >> 2;
    const int part = blockIdx.x & 3;
    const int t    = threadIdx.x;
    const int lane = t & 31;
    const int w    = t >> 5;

    __shared__ float sb[NK];
    __shared__ float sred[NK][9];
    if (t < NK) sb[t] = g_sums[t * CH + c] * g_scale[t] * SB_FACT;
    __syncthreads();

    float bsr[NK];
    #pragma unroll
    for (int k = 0; k < NK; k++) bsr[k] = sb[k];
    float acc[NK];
    #pragma unroll
    for (int k = 0; k < NK; k++) acc[k] = 0.0f;

    const int qs = part * QCHUNK;
    const int qe = (qs + QCHUNK < NQ) ? qs + QCHUNK : NQ;
    for (int q = qs + t; q < qe; q += 256) {
        float qv[NK];
        #pragma unroll
        for (int k = 0; k < NK; k++)
            qv[k] = queues[(k * CH + c) * NQ + q];
        if (part == 0 && q == 0) {
            #pragma unroll
            for (int k = 0; k < NK; k++) g_sbq0[k * CH + c] = bsr[k] * qv[k];
        }
        float qsum = 0.0f;
        #pragma unroll
        for (int k = 0; k < NK; k++) qsum += qv[k];
        #pragma unroll
        for (int k = 0; k < NK; k++) {
            float u  = bsr[k] * qv[k];
            float wv = bsr[k] * qsum - u;
            acc[k] += ex2f(u) + ex2f(wv);
        }
    }
    #pragma unroll
    for (int k = 0; k < NK; k++) {
        #pragma unroll
        for (int off = 16; off > 0; off >>= 1)
            acc[k] += __shfl_xor_sync(0xffffffffu, acc[k], off);
    }
    if (lane == 0) {
        #pragma unroll
        for (int k = 0; k < NK; k++) sred[k][w] = acc[k];
    }
    __syncthreads();
    if (t < NK) {
        float tot = 0.0f;
        #pragma unroll
        for (int j = 0; j < 8; j++) tot += sred[t][j];
        g_lsepart[(part * NK + t) * CH + c] = tot;
    }
}

// ============================================================
// Kernel 4: combine q-parts -> contrib -> loss scalar.
// ============================================================
__global__ void k4_loss(float* __restrict__ out_loss) {
    const int t = threadIdx.x;      // t = channel
    const int lane = t & 31;
    const int w = t >> 5;
    __shared__ float red[NK][9];

    float contrib[NK];
    #pragma unroll
    for (int k = 0; k < NK; k++) {
        float tot = 0.0f;
        #pragma unroll
        for (int j = 0; j < QPARTS; j++) tot += g_lsepart[(j * NK + k) * CH + t];
        contrib[k] = (log2f(tot) - g_sbq0[k * CH + t]) * LN2;
    }
    #pragma unroll
    for (int k = 0; k < NK; k++) {
        float s = contrib[k];
        #pragma unroll
        for (int off = 16; off > 0; off >>= 1)
            s += __shfl_xor_sync(0xffffffffu, s, off);
        if (lane == 0) red[k][w] = s;
    }
    __syncthreads();
    if (t == 0) {
        float loss = 0.0f;
        #pragma unroll
        for (int k = 0; k < NK; k++) {
            float s = 0.0f;
            #pragma unroll
            for (int j = 0; j < 8; j++) s += red[k][j];
            loss += g_present[k] * s * (1.0f / CH);
        }
        *out_loss = loss;
    }
}

extern "C" void kernel_launch(void* const* d_in, const int* in_sizes, int n_in,
                              void* d_out, int out_size) {
    const float* fea    = (const float*)d_in[0];
    const float* res    = (const float*)d_in[1];
    const float* queues = (const float*)d_in[2];
    float* out = (float*)d_out;
    float* out_loss = out + (out_size - 1);

    cudaFuncSetAttribute(k1_fused, cudaFuncAttributeMaxDynamicSharedMemorySize,
                         K1_SMEM_BYTES);

    k1_fused<<<NBLK1, 256, K1_SMEM_BYTES>>>(fea, res, out);
    k2a_reduce<<<NK * 8, 256>>>();
    k2b_scale<<<1, 256>>>();
    k3_lse<<<CH * QPARTS, 256>>>(queues);
    k4_loss<<<1, 256>>>(out_loss);
}

// round 7
// speedup vs baseline: 5.4867x; 1.5343x over previous
#include <cuda_runtime.h>
#include <cstdint>

#define BS 8
#define CH 256
#define HW 16384
#define NK 19
#define NQ 2975
#define LOG2E 1.4426950408889634f
#define LN2   0.6931471805599453f
#define SB_FACT (5.0f * LOG2E)      /* (1/T) * log2(e) */

#define NBLK1 296
#define NSTRIPS (BS * HW / 64)      /* 2048 strips of 64 px */
#define CST2 257                    /* ssum row stride (odd) */
#define T4ST 17                     /* tile row stride in float4 (odd) */

#define QPARTS 4
#define QCHUNK 744

/* dynamic smem layout for k1 (in 4-byte words) */
#define TILE_OFF  0                 /* 256 * 17 float4 = 17408 words */
#define SSUM_OFF  17408             /* 19*257 = 4883 words */
#define SV_OFF    22291             /* 4*64 */
#define SBK_OFF   22547             /* 4*64 */
#define SPRED_OFF 22803             /* 16 words */
#define K1_WORDS  22819
#define K1_SMEM_BYTES (K1_WORDS * 4)

/* ---------------- device scratch ---------------- */
__device__ float g_partial[NBLK1 * NK * CH];
__device__ int   g_cnt[NBLK1 * NK];
__device__ float g_sums[NK * CH];
__device__ float g_sqpart[NK * 8];
__device__ float g_scale[NK];
__device__ float g_present[NK];
__device__ float g_lsepart[QPARTS * NK * CH];
__device__ float g_sbq0[NK * CH];

__device__ __forceinline__ float ex2f(float x) {
    float y; asm("ex2.approx.ftz.f32 %0, %1;" : "=f"(y) : "f"(x)); return y;
}

// ============================================================
// Kernel 1: fused argmax + res->out copy + per-class channel sums.
// Block = 256 threads, strip = 64 pixels of one image.
// ============================================================
__global__ __launch_bounds__(256, 2)
void k1_fused(const float* __restrict__ fea,
              const float* __restrict__ res,
              float* __restrict__ out) {
    extern __shared__ float sm[];
    float4* tile4 = (float4*)(sm + TILE_OFF);
    float*  ssum  = sm + SSUM_OFF;
    float*  sv2   = sm + SV_OFF;
    int*    sbk2  = (int*)(sm + SBK_OFF);
    unsigned char* spred  = (unsigned char*)(sm + SPRED_OFF);
    unsigned*      spredw = (unsigned*)(sm + SPRED_OFF);

    const int tid  = threadIdx.x;
    const int lane = tid & 31;
    const int w    = tid >> 5;

    for (int i = tid; i < NK * CST2; i += 256) ssum[i] = 0.0f;
    int creg = 0;                       // warp-0 lanes < NK: class counts
    __syncthreads();

    const int px_r = tid & 63;          // res-phase pixel within strip
    const int ks   = tid >> 6;          // k-slice 0..3
    const int arow = tid >> 2;          // stage-A row within a 64-row pass
    const int acol = (tid & 3) << 2;    // stage-A float4 column base

    for (int s = blockIdx.x; s < NSTRIPS; s += NBLK1) {
        const int b  = s >> 8;
        const int p0 = (s & 255) << 6;

        // ---- res phase: copy + per-slice argmax (k = ks, ks+4, ...) ----
        float bv = -3.4e38f; int bk = NK;
        #pragma unroll
        for (int j = 0; j < 5; j++) {
            int k = ks + (j << 2);
            if (k < NK) {
                int idx = ((b * NK + k) << 14) + p0 + px_r;
                float v = res[idx];
                out[idx] = v;
                if (v > bv) { bv = v; bk = k; }   // ascending k: first max wins
            }
        }
        sv2[(ks << 6) + px_r] = bv;
        sbk2[(ks << 6) + px_r] = bk;

        // ---- stage A: fea tile (256 ch x 64 px) -> smem as float4 ----
        // 4 threads per row; 8 independent LDG.128 batched before stores.
        const float4* fb4 = (const float4*)(fea + (((long)(b * CH)) << 14) + p0);
        #pragma unroll
        for (int half = 0; half < 2; half++) {
            float4 v[8];
            #pragma unroll
            for (int pp = 0; pp < 2; pp++) {
                int row = arow + ((half * 2 + pp) << 6);
                const float4* fr = fb4 + (long)row * (HW / 4) + acol;
                v[pp * 4 + 0] = fr[0];
                v[pp * 4 + 1] = fr[1];
                v[pp * 4 + 2] = fr[2];
                v[pp * 4 + 3] = fr[3];
            }
            #pragma unroll
            for (int pp = 0; pp < 2; pp++) {
                int row = arow + ((half * 2 + pp) << 6);
                float4* tr = tile4 + row * T4ST + acol;
                tr[0] = v[pp * 4 + 0];
                tr[1] = v[pp * 4 + 1];
                tr[2] = v[pp * 4 + 2];
                tr[3] = v[pp * 4 + 3];
            }
        }
        __syncthreads();

        // ---- combine slice argmaxes -> spred bytes ----
        if (tid < 64) {
            float Bv = sv2[tid]; int Bk = sbk2[tid];
            #pragma unroll
            for (int j = 1; j < 4; j++) {
                float v = sv2[(j << 6) + tid]; int kk = sbk2[(j << 6) + tid];
                if (v > Bv || (v == Bv && kk < Bk)) { Bv = v; Bk = kk; }
            }
            spred[tid] = (unsigned char)Bk;
        }
        __syncthreads();

        // ---- stage C: thread = channel, 16 x LDS.128 (4 px each) ----
        const int cs = tid * T4ST;
        #pragma unroll 4
        for (int s4 = 0; s4 < 16; s4++) {
            float4 v = tile4[cs + s4];
            unsigned pw = spredw[s4];
            int p0c = pw & 0xFF;
            int p1c = (pw >> 8) & 0xFF;
            int p2c = (pw >> 16) & 0xFF;
            int p3c = pw >> 24;
            ssum[p0c * CST2 + tid] += v.x;
            ssum[p1c * CST2 + tid] += v.y;
            ssum[p2c * CST2 + tid] += v.z;
            ssum[p3c * CST2 + tid] += v.w;
            if (w == 0) {
                creg += (p0c == lane) ? 1 : 0;
                creg += (p1c == lane) ? 1 : 0;
                creg += (p2c == lane) ? 1 : 0;
                creg += (p3c == lane) ? 1 : 0;
            }
        }
        __syncthreads();
    }

    // ---- flush partials ----
    for (int i = tid; i < NK * CH; i += 256) {
        int k = i >> 8, c = i & 255;
        g_partial[blockIdx.x * (NK * CH) + i] = ssum[k * CST2 + c];
    }
    if (w == 0 && lane < NK) g_cnt[blockIdx.x * NK + lane] = creg;
}

// ============================================================
// Kernel 2a: reduce partials -> g_sums + per-(k,chunk) sum of squares.
// ============================================================
__global__ void k2a_reduce() {
    const int k = blockIdx.x >> 3;
    const int chunk = blockIdx.x & 7;
    const int lane = threadIdx.x & 31;
    const int g = threadIdx.x >> 5;
    const int c = chunk * 32 + lane;

    float s = 0.0f;
    for (int blk = g; blk < NBLK1; blk += 8)
        s += g_partial[blk * (NK * CH) + k * CH + c];
    __shared__ float smr[8][33];
    smr[g][lane] = s;
    __syncthreads();
    if (g == 0) {
        float tot = 0.0f;
        #pragma unroll
        for (int j = 0; j < 8; j++) tot += smr[j][lane];
        g_sums[k * CH + c] = tot;
        float sq = tot * tot;
        #pragma unroll
        for (int off = 16; off > 0; off >>= 1) sq += __shfl_xor_sync(0xffffffffu, sq, off);
        if (lane == 0) g_sqpart[k * 8 + chunk] = sq;
    }
}

// ============================================================
// Kernel 2b: counts + per-class key scale + present flags.
// keys = normalize(sums/max(cnt,1)) = sums / max(||sums||, max(cnt,1)*1e-12)
// ============================================================
__global__ void k2b_scale() {
    __shared__ int scnt2[NK][8];
    const int t = threadIdx.x;
    if (t < NK * 8) {
        int k = t >> 3, part = t & 7;
        int cs = 0;
        for (int blk = part; blk < NBLK1; blk += 8) cs += g_cnt[blk * NK + k];
        scnt2[k][part] = cs;
    }
    __syncthreads();
    if (t < NK) {
        int cnt = 0;
        #pragma unroll
        for (int j = 0; j < 8; j++) cnt += scnt2[t][j];
        float sq = 0.0f;
        #pragma unroll
        for (int j = 0; j < 8; j++) sq += g_sqpart[t * 8 + j];
        float nrm = sqrtf(sq);
        float cp = fmaxf((float)cnt, 1.0f);
        g_scale[t] = 1.0f / fmaxf(nrm, cp * 1e-12f);
        g_present[t] = (cnt > 0) ? 1.0f : 0.0f;
    }
}

// ============================================================
// Kernel 3: partial exp-sums over a quarter of the 2Q logits.
// grid = 256 channels x 4 q-parts.
// ============================================================
__global__ __launch_bounds__(256) void k3_lse(const float* __restrict__ queues) {
    const int c    = blockIdx.x >> 2;
    const int part = blockIdx.x & 3;
    const int t    = threadIdx.x;
    const int lane = t & 31;
    const int w    = t >> 5;

    __shared__ float sb[NK];
    __shared__ float sred[NK][9];
    if (t < NK) sb[t] = g_sums[t * CH + c] * g_scale[t] * SB_FACT;
    __syncthreads();

    float bsr[NK];
    #pragma unroll
    for (int k = 0; k < NK; k++) bsr[k] = sb[k];
    float acc[NK];
    #pragma unroll
    for (int k = 0; k < NK; k++) acc[k] = 0.0f;

    const int qs = part * QCHUNK;
    const int qe = (qs + QCHUNK < NQ) ? qs + QCHUNK : NQ;
    for (int q = qs + t; q < qe; q += 256) {
        float qv[NK];
        #pragma unroll
        for (int k = 0; k < NK; k++)
            qv[k] = queues[(k * CH + c) * NQ + q];
        if (part == 0 && q == 0) {
            #pragma unroll
            for (int k = 0; k < NK; k++) g_sbq0[k * CH + c] = bsr[k] * qv[k];
        }
        float qsum = 0.0f;
        #pragma unroll
        for (int k = 0; k < NK; k++) qsum += qv[k];
        #pragma unroll
        for (int k = 0; k < NK; k++) {
            float u  = bsr[k] * qv[k];
            float wv = bsr[k] * qsum - u;
            acc[k] += ex2f(u) + ex2f(wv);
        }
    }
    #pragma unroll
    for (int k = 0; k < NK; k++) {
        #pragma unroll
        for (int off = 16; off > 0; off >>= 1)
            acc[k] += __shfl_xor_sync(0xffffffffu, acc[k], off);
    }
    if (lane == 0) {
        #pragma unroll
        for (int k = 0; k < NK; k++) sred[k][w] = acc[k];
    }
    __syncthreads();
    if (t < NK) {
        float tot = 0.0f;
        #pragma unroll
        for (int j = 0; j < 8; j++) tot += sred[t][j];
        g_lsepart[(part * NK + t) * CH + c] = tot;
    }
}

// ============================================================
// Kernel 4: combine q-parts -> contrib -> loss scalar.
// ============================================================
__global__ void k4_loss(float* __restrict__ out_loss) {
    const int t = threadIdx.x;      // t = channel
    const int lane = t & 31;
    const int w = t >> 5;
    __shared__ float red[NK][9];

    float contrib[NK];
    #pragma unroll
    for (int k = 0; k < NK; k++) {
        float tot = 0.0f;
        #pragma unroll
        for (int j = 0; j < QPARTS; j++) tot += g_lsepart[(j * NK + k) * CH + t];
        contrib[k] = (log2f(tot) - g_sbq0[k * CH + t]) * LN2;
    }
    #pragma unroll
    for (int k = 0; k < NK; k++) {
        float s = contrib[k];
        #pragma unroll
        for (int off = 16; off > 0; off >>= 1)
            s += __shfl_xor_sync(0xffffffffu, s, off);
        if (lane == 0) red[k][w] = s;
    }
    __syncthreads();
    if (t == 0) {
        float loss = 0.0f;
        #pragma unroll
        for (int k = 0; k < NK; k++) {
            float s = 0.0f;
            #pragma unroll
            for (int j = 0; j < 8; j++) s += red[k][j];
            loss += g_present[k] * s * (1.0f / CH);
        }
        *out_loss = loss;
    }
}

extern "C" void kernel_launch(void* const* d_in, const int* in_sizes, int n_in,
                              void* d_out, int out_size) {
    const float* fea    = (const float*)d_in[0];
    const float* res    = (const float*)d_in[1];
    const float* queues = (const float*)d_in[2];
    float* out = (float*)d_out;
    float* out_loss = out + (out_size - 1);

    cudaFuncSetAttribute(k1_fused, cudaFuncAttributeMaxDynamicSharedMemorySize,
                         K1_SMEM_BYTES);

    k1_fused<<<NBLK1, 256, K1_SMEM_BYTES>>>(fea, res, out);
    k2a_reduce<<<NK * 8, 256>>>();
    k2b_scale<<<1, 256>>>();
    k3_lse<<<CH * QPARTS, 256>>>(queues);
    k4_loss<<<1, 256>>>(out_loss);
}